// round 13
// baseline (speedup 1.0000x reference)
#include <cuda_runtime.h>
#include <cstdint>

#define B_SZ    16
#define IN_F    8192
#define OUT_F   8192
#define GRP     128
#define NGRP    64
#define THREADS 320            // 8 consumer warps + W-producer warp + x-producer warp
#define RPB     32             // rows per CTA  -> grid 256, 2 CTAs/SM
#define WST     4              // W ring stages
#define XST     3              // x ring stages
#define XPAD    20             // 80B col stride -> conflict-free LDS.128

#define WS_STAGE_F  (RPB * GRP)        // 4096 floats (16 KB) per W stage
#define XR_STAGE_F  (GRP * XPAD)       // 2560 floats (10 KB) per x stage
#define WS_OFF      1024
#define XR_OFF      (WS_OFF + WST * WS_STAGE_F * 4)   // 66560
#define SC_OFF      (XR_OFF + XST * XR_STAGE_F * 4)   // 97280
#define SMEM_TOTAL  (SC_OFF + RPB * NGRP * 4)         // 105472  (2 CTAs/SM)

typedef unsigned long long ull;

__device__ float g_xT[IN_F * B_SZ];    // pre-transposed x [8192][16]

__device__ __forceinline__ ull pack2(float v) {
    ull r; asm("mov.b64 %0, {%1, %1};" : "=l"(r) : "f"(v)); return r;
}
__device__ __forceinline__ void fma2(ull& d, ull a, ull b) {
    asm("fma.rn.f32x2 %0, %1, %2, %0;" : "+l"(d) : "l"(a), "l"(b));
}
__device__ __forceinline__ ull add2(ull a, ull b) {
    ull r; asm("add.rn.f32x2 %0, %1, %2;" : "=l"(r) : "l"(a), "l"(b)); return r;
}
__device__ __forceinline__ void unpack2(ull v, float& lo, float& hi) {
    asm("mov.b64 {%0, %1}, %2;" : "=f"(lo), "=f"(hi) : "l"(v));
}
__device__ __forceinline__ void cp_async16(uint32_t dst, const float* src) {
    asm volatile("cp.async.cg.shared.global [%0], [%1], 16;" :: "r"(dst), "l"(src));
}
__device__ __forceinline__ void mbar_init(uint32_t a, uint32_t cnt) {
    asm volatile("mbarrier.init.shared.b64 [%0], %1;" :: "r"(a), "r"(cnt) : "memory");
}
__device__ __forceinline__ void mbar_arrive(uint32_t a) {
    asm volatile("mbarrier.arrive.release.cta.shared::cta.b64 _, [%0];" :: "r"(a) : "memory");
}
__device__ __forceinline__ void cpasync_mbar_arrive_noinc(uint32_t a) {
    asm volatile("cp.async.mbarrier.arrive.noinc.shared::cta.b64 [%0];" :: "r"(a) : "memory");
}
__device__ __forceinline__ void mbar_wait(uint32_t a, uint32_t parity) {
    asm volatile(
        "{\n\t.reg .pred P;\n\t"
        "WL_%=:\n\t"
        "mbarrier.try_wait.parity.acquire.cta.shared::cta.b64 P, [%0], %1, 0x989680;\n\t"
        "@P bra.uni WD_%=;\n\t"
        "bra.uni WL_%=;\n\t"
        "WD_%=:\n\t}"
        :: "r"(a), "r"(parity) : "memory");
}

// ---- pre-pass: x [16][8192] -> g_xT [8192][16]
__global__ void __launch_bounds__(256, 1)
transpose_x_kernel(const float* __restrict__ x)
{
    const int col = blockIdx.x * 256 + threadIdx.x;
    float v[B_SZ];
#pragma unroll
    for (int b = 0; b < B_SZ; b++) v[b] = __ldg(x + (size_t)b * IN_F + col);
    float4* dst = reinterpret_cast<float4*>(g_xT + (size_t)col * B_SZ);
#pragma unroll
    for (int q = 0; q < 4; q++)
        dst[q] = make_float4(v[4*q], v[4*q+1], v[4*q+2], v[4*q+3]);
}

__global__ void __launch_bounds__(THREADS, 2)
axcore_linear_kernel(const float* __restrict__ W,
                     const float* __restrict__ scale,
                     const float* __restrict__ bias,
                     float* __restrict__ out)
{
    extern __shared__ char smem[];
    float* ws = reinterpret_cast<float*>(smem + WS_OFF);
    float* xr = reinterpret_cast<float*>(smem + XR_OFF);
    float* sc = reinterpret_cast<float*>(smem + SC_OFF);
    const uint32_t smem_u32 = (uint32_t)__cvta_generic_to_shared(smem);
#define FULLW(s)  (smem_u32 + (s) * 8)         // cnt 32, noinc
#define EMPTYW(s) (smem_u32 + 32 + (s) * 8)    // cnt 8, elected
#define FULLX(s)  (smem_u32 + 64 + (s) * 8)    // cnt 32, noinc
#define EMPTYX(s) (smem_u32 + 88 + (s) * 8)    // cnt 8, elected

    const int tid  = threadIdx.x;
    const int lane = tid & 31;
    const int warp = tid >> 5;
    const int row0 = blockIdx.x * RPB;
    const float* Wb = W + (size_t)row0 * IN_F;

    if (tid == 0) {
#pragma unroll
        for (int s = 0; s < WST; s++) {
            mbar_init(FULLW(s), 32);
            mbar_init(EMPTYW(s), 8);
        }
#pragma unroll
        for (int s = 0; s < XST; s++) {
            mbar_init(FULLX(s), 32);
            mbar_init(EMPTYX(s), 8);
        }
    }
    // ---- stage scales (all threads), then sync covers barrier init too
    for (int i = tid; i < RPB * NGRP; i += THREADS)
        sc[i] = scale[(size_t)row0 * NGRP + i];
    __syncthreads();

    if (warp == 8) {
        // ---- W producer: fully self-paced 4-stage ring
        for (int g = 0; g < NGRP; g++) {
            const int s = g & 3;
            mbar_wait(EMPTYW(s), ((g >> 2) & 1) ^ 1);   // immediate for g<4
            const float* src = Wb + (size_t)g * GRP;
            const uint32_t db = smem_u32 + WS_OFF + s * (WS_STAGE_F * 4);
#pragma unroll
            for (int j = 0; j < 32; j++) {              // 32 rows x 32 x 16B
                cp_async16(db + (uint32_t)(j * GRP + lane * 4) * 4,
                           src + (size_t)j * IN_F + lane * 4);
            }
            cpasync_mbar_arrive_noinc(FULLW(s));
        }
        return;
    }
    if (warp == 9) {
        // ---- x producer: 3-stage ring from g_xT, [col][XPAD] layout
        for (int g = 0; g < NGRP; g++) {
            const int s = g % 3;
            mbar_wait(EMPTYX(s), (((g / 3) & 1)) ^ 1);  // immediate for g<3
            const float* src = g_xT + (size_t)g * GRP * B_SZ;
            const uint32_t db = smem_u32 + XR_OFF + s * (XR_STAGE_F * 4);
#pragma unroll
            for (int j = 0; j < 16; j++) {
                const int i = lane + 32 * j;            // 0..511
                const int col = i >> 2, q = i & 3;      // 128 cols x 4 x 16B
                cp_async16(db + (uint32_t)(col * XPAD + q * 4) * 4,
                           src + col * B_SZ + q * 4);
            }
            cpasync_mbar_arrive_noinc(FULLX(s));
        }
        return;
    }

    // ---- consumers: warps 0..7; tile 8 rows x 8 batches
    const int half = warp >> 2;          // batch half (warps 0-3: b0-7, 4-7: b8-15)
    const int wr0  = (warp & 3) * 8;     // warp's first row in CTA

    ull acc[8][4];
#pragma unroll
    for (int r = 0; r < 8; r++)
#pragma unroll
        for (int q = 0; q < 4; q++) acc[r][q] = 0ull;

    for (int g = 0; g < NGRP; g++) {
        const int sw = g & 3, sx = g % 3;
        mbar_wait(FULLW(sw), (g >> 2) & 1);
        mbar_wait(FULLX(sx), (g / 3) & 1);

        const float* wst = ws + sw * WS_STAGE_F + wr0 * GRP;
        const float* xb  = xr + sx * XR_STAGE_F + half * 8;
        float s[8];
#pragma unroll
        for (int r = 0; r < 8; r++) s[r] = sc[(wr0 + r) * NGRP + g];

#pragma unroll
        for (int k = 0; k < 4; k++) {
            const int kc = lane + 32 * k;           // column within group
            const float* xp = xb + kc * XPAD;
            ulonglong2 va = *reinterpret_cast<const ulonglong2*>(xp);
            ulonglong2 vb = *reinterpret_cast<const ulonglong2*>(xp + 4);
            ull x2[4] = { va.x, va.y, vb.x, vb.y };
#pragma unroll
            for (int r = 0; r < 8; r++) {
                const ull w2 = pack2(wst[r * GRP + kc] * s[r]);
#pragma unroll
                for (int q = 0; q < 4; q++) fma2(acc[r][q], w2, x2[q]);
            }
        }

        if (lane == 0) {
            mbar_arrive(EMPTYW(sw));
            mbar_arrive(EMPTYX(sx));
        }
    }

    // ---- butterfly reduction across lanes
#pragma unroll
    for (int r = 0; r < 8; r++)
#pragma unroll
        for (int q = 0; q < 4; q++) {
            ull v = acc[r][q];
#pragma unroll
            for (int off = 16; off > 0; off >>= 1)
                v = add2(v, __shfl_xor_sync(0xffffffffu, v, off));
            acc[r][q] = v;
        }

    // ---- writeback: lane (r*4+q) -> row wr0+r, batches (half*8+2q, +1)
#pragma unroll
    for (int r = 0; r < 8; r++)
#pragma unroll
        for (int q = 0; q < 4; q++)
            if (lane == r * 4 + q) {
                const int row = row0 + wr0 + r;
                const int b0  = half * 8 + 2 * q;
                const float bv = __ldg(bias + row);
                float lo, hi;
                unpack2(acc[r][q], lo, hi);
                out[(size_t)b0 * OUT_F + row]       = lo + bv;
                out[(size_t)(b0 + 1) * OUT_F + row] = hi + bv;
            }
}

extern "C" void kernel_launch(void* const* d_in, const int* in_sizes, int n_in,
                              void* d_out, int out_size)
{
    const float* x     = (const float*)d_in[0]; // [16, 8192]
    const float* W     = (const float*)d_in[1]; // [8192, 8192]
    const float* scale = (const float*)d_in[2]; // [8192, 64]
    const float* bias  = (const float*)d_in[3]; // [1, 8192]
    // d_in[4] = types — constant lookup in reference; no float math: unused
    float* out = (float*)d_out;                 // [16, 8192]

    cudaFuncSetAttribute(axcore_linear_kernel,
                         cudaFuncAttributeMaxDynamicSharedMemorySize, SMEM_TOTAL);

    transpose_x_kernel<<<IN_F / 256, 256>>>(x);
    axcore_linear_kernel<<<OUT_F / RPB, THREADS, SMEM_TOTAL>>>(W, scale, bias, out);
}